// round 1
// baseline (speedup 1.0000x reference)
#include <cuda_runtime.h>
#include <cub/cub.cuh>

#define Bb   32
#define Nn   2048
#define Ff   1024
#define HSd  8192
#define HFd  4096
#define OUTF 1024
#define M1   (Bb * Ff)   // 32768 rows for sorted-MLP (K = Nn)
#define M2   (Bb * Nn)   // 65536 rows for feature-MLP (K = Ff)

// ---------------- static device scratch (no allocations allowed) ----------------
__device__ float g_big[268435456]; // 1 GiB: h (M1 x HSd), reused as h2 (M2 x HFd)
__device__ float g_xt [67108864];  // xt [B,F,N], reused as y_s
__device__ float g_xs [67108864];  // xs [B,F,N], reused as yg
__device__ int   g_p  [67108864];  // permutation p [B,F,N]

// ---------------- transpose: x[B,N,F] -> xt[B,F,N] ----------------
__global__ void transpose_kernel(const float* __restrict__ x, float* __restrict__ xt) {
    __shared__ float tile[32][33];
    int b  = blockIdx.z;
    int n0 = blockIdx.y * 32;
    int f0 = blockIdx.x * 32;
    int tx = threadIdx.x, ty = threadIdx.y; // block (32, 8)
    const float* xb  = x  + (long)b * Nn * Ff;
    float*       xtb = xt + (long)b * Ff * Nn;
#pragma unroll
    for (int i = 0; i < 32; i += 8)
        tile[ty + i][tx] = xb[(long)(n0 + ty + i) * Ff + f0 + tx];
    __syncthreads();
#pragma unroll
    for (int i = 0; i < 32; i += 8)
        xtb[(long)(f0 + ty + i) * Nn + n0 + tx] = tile[tx][ty + i];
}

// ---------------- per-row stable argsort (radix) ----------------
// Produces p = argsort(row) and xs with xs[j] = row[rank(j)]  (== torch scatter(-1, p, row))
__global__ void __launch_bounds__(512) sort_kernel(const float* __restrict__ xt,
                                                   float* __restrict__ xs,
                                                   int* __restrict__ p) {
    typedef cub::BlockRadixSort<unsigned int, 512, 4, int> BRS;
    __shared__ typename BRS::TempStorage ts;
    __shared__ float rowv[Nn];
    __shared__ int   inv[Nn];

    long row = blockIdx.x;
    const float* in = xt + row * Nn;

    float4 v4 = reinterpret_cast<const float4*>(in)[threadIdx.x];
    float vj[4] = {v4.x, v4.y, v4.z, v4.w};

    unsigned keys[4]; int vals[4];
#pragma unroll
    for (int j = 0; j < 4; ++j) {
        int idx = threadIdx.x * 4 + j;
        rowv[idx] = vj[j];
        unsigned u = __float_as_uint(vj[j]);
        u = (u & 0x80000000u) ? ~u : (u | 0x80000000u); // order-preserving key transform
        keys[j] = u; vals[j] = idx;
    }
    __syncthreads();
    BRS(ts).Sort(keys, vals); // stable ascending -> matches jnp.argsort incl. ties
    __syncthreads();

    int4 pv;
    pv.x = vals[0]; pv.y = vals[1]; pv.z = vals[2]; pv.w = vals[3];
    reinterpret_cast<int4*>(p + row * Nn)[threadIdx.x] = pv;
#pragma unroll
    for (int j = 0; j < 4; ++j)
        inv[vals[j]] = threadIdx.x * 4 + j; // inv = rank
    __syncthreads();

    float4 o;
    o.x = rowv[inv[threadIdx.x * 4 + 0]];
    o.y = rowv[inv[threadIdx.x * 4 + 1]];
    o.z = rowv[inv[threadIdx.x * 4 + 2]];
    o.w = rowv[inv[threadIdx.x * 4 + 3]];
    reinterpret_cast<float4*>(xs + row * Nn)[threadIdx.x] = o;
}

// ---------------- per-row gather: yg[row, n] = y_s[row, p[row, n]] ----------------
__global__ void gather_kernel(const float* __restrict__ ys, const int* __restrict__ p,
                              float* __restrict__ yg) {
    __shared__ float sm[Nn];
    long row = blockIdx.x;
    for (int i = threadIdx.x; i < Nn; i += blockDim.x)
        sm[i] = ys[row * Nn + i];
    __syncthreads();
    for (int i = threadIdx.x; i < Nn; i += blockDim.x)
        yg[row * Nn + i] = sm[p[row * Nn + i]];
}

// ---------------- SIMT GEMM: C[M,Nc] = epi(A @ W^T + bias (+skip)) ----------------
// A row-major [M,K] (or, if ACOL, batched column-major: A[m,k] = buf[(m>>11)*K*2048 + k*2048 + (m&2047)])
// W row-major [Nc,K] (torch Linear weight). 128x128 tile, BK=16, 8x8 per thread.
// Supertiling: m-fastest within superM-column -> A panels + W stay L2-resident.
template<bool ACOL, bool RELU, bool SKIP>
__global__ void __launch_bounds__(256, 2) gemm128(
    const float* __restrict__ A, const float* __restrict__ W,
    const float* __restrict__ bias, const float* __restrict__ skip,
    float* __restrict__ C, int M, int Nc, int K, int superM)
{
    __shared__ float As[16][128];
    __shared__ float Bs[16][128];
    const int nTN = Nc >> 7;
    int tilesPer = superM * nTN;
    int sid = blockIdx.x / tilesPer;
    int rem = blockIdx.x - sid * tilesPer;
    int mt  = sid * superM + (rem % superM);
    int nt  = rem / superM;
    int m0 = mt << 7, n0 = nt << 7;

    int t  = threadIdx.x;
    int tx = t & 15, ty = t >> 4;

    float acc[8][8];
#pragma unroll
    for (int i = 0; i < 8; ++i)
#pragma unroll
        for (int j = 0; j < 8; ++j) acc[i][j] = 0.f;

    const float* Wt = W + (long)n0 * K;
    long abase = 0;
    if (ACOL) abase = (long)(m0 >> 11) * ((long)K * 2048) + (m0 & 2047);

    for (int k0 = 0; k0 < K; k0 += 16) {
#pragma unroll
        for (int q = 0; q < 2; ++q) {
            int idx = t + q * 256;
            int r = idx >> 2, c4 = idx & 3;
            if (!ACOL) {
                float4 v = *(const float4*)(A + (long)(m0 + r) * K + k0 + c4 * 4);
                As[c4 * 4 + 0][r] = v.x; As[c4 * 4 + 1][r] = v.y;
                As[c4 * 4 + 2][r] = v.z; As[c4 * 4 + 3][r] = v.w;
            } else {
                int kk = idx >> 5, mq = idx & 31;
                float4 v = *(const float4*)(A + abase + (long)(k0 + kk) * 2048 + mq * 4);
                *(float4*)&As[kk][mq * 4] = v;
            }
            float4 w = *(const float4*)(Wt + (long)r * K + k0 + c4 * 4);
            Bs[c4 * 4 + 0][r] = w.x; Bs[c4 * 4 + 1][r] = w.y;
            Bs[c4 * 4 + 2][r] = w.z; Bs[c4 * 4 + 3][r] = w.w;
        }
        __syncthreads();
#pragma unroll
        for (int kk = 0; kk < 16; ++kk) {
            float a[8], b[8];
            *(float4*)&a[0] = *(const float4*)&As[kk][ty * 8];
            *(float4*)&a[4] = *(const float4*)&As[kk][ty * 8 + 4];
            *(float4*)&b[0] = *(const float4*)&Bs[kk][tx * 8];
            *(float4*)&b[4] = *(const float4*)&Bs[kk][tx * 8 + 4];
#pragma unroll
            for (int i = 0; i < 8; ++i)
#pragma unroll
                for (int j = 0; j < 8; ++j)
                    acc[i][j] = fmaf(a[i], b[j], acc[i][j]);
        }
        __syncthreads();
    }

    float bi[8];
#pragma unroll
    for (int j = 0; j < 8; ++j) bi[j] = bias[n0 + tx * 8 + j];
#pragma unroll
    for (int i = 0; i < 8; ++i) {
        long off = (long)(m0 + ty * 8 + i) * Nc + n0 + tx * 8;
        float outv[8];
#pragma unroll
        for (int j = 0; j < 8; ++j) {
            float v = acc[i][j] + bi[j];
            if (SKIP) v += skip[off + j];
            if (RELU) v = fmaxf(v, 0.f);
            outv[j] = v;
        }
        *(float4*)(C + off)     = *(float4*)&outv[0];
        *(float4*)(C + off + 4) = *(float4*)&outv[4];
    }
}

// ---------------- launch ----------------
extern "C" void kernel_launch(void* const* d_in, const int* in_sizes, int n_in,
                              void* d_out, int out_size) {
    const float* x   = (const float*)d_in[0];
    const float* sw1 = (const float*)d_in[1];
    const float* sb1 = (const float*)d_in[2];
    const float* sw2 = (const float*)d_in[3];
    const float* sb2 = (const float*)d_in[4];
    const float* fw1 = (const float*)d_in[5];
    const float* fb1 = (const float*)d_in[6];
    const float* fw2 = (const float*)d_in[7];
    const float* fb2 = (const float*)d_in[8];
    float* out = (float*)d_out;

    float *xt_p, *xs_p, *big_p; int *p_p;
    cudaGetSymbolAddress((void**)&xt_p,  g_xt);
    cudaGetSymbolAddress((void**)&xs_p,  g_xs);
    cudaGetSymbolAddress((void**)&big_p, g_big);
    cudaGetSymbolAddress((void**)&p_p,   g_p);

    // 1) transpose x -> xt[B,F,N]
    dim3 tb(32, 8), tg(Ff / 32, Nn / 32, Bb);
    transpose_kernel<<<tg, tb>>>(x, xt_p);

    // 2) per-row sort: xs (permuted values) + p (argsort)
    sort_kernel<<<M1, 512>>>(xt_p, xs_p, p_p);

    // 3) h = relu(xs @ sw1^T + sb1)            [M1, HSd]
    gemm128<false, true, false><<<(M1 / 128) * (HSd / 128), 256>>>(
        xs_p, sw1, sb1, nullptr, big_p, M1, HSd, Nn, 32);

    // 4) y_s = h @ sw2^T + sb2 + xs            [M1, Nn]  (into xt buffer)
    gemm128<false, false, true><<<(M1 / 128) * (Nn / 128), 256>>>(
        big_p, sw2, sb2, xs_p, xt_p, M1, Nn, HSd, 8);

    // 5) yg[row, n] = y_s[row, p[row, n]]      [B,F,N]   (into xs buffer)
    gather_kernel<<<M1, 256>>>(xt_p, p_p, xs_p);

    // 6) h2 = relu(yt @ fw1^T + fb1), yt[b,n,f] = yg[b,f,n] read column-major (no transpose)
    gemm128<true, true, false><<<(M2 / 128) * (HFd / 128), 256>>>(
        xs_p, fw1, fb1, nullptr, big_p, M2, HFd, Ff, 64);

    // 7) out = h2 @ fw2^T + fb2                [B,N,OUT]
    gemm128<false, false, false><<<(M2 / 128) * (OUTF / 128), 256>>>(
        big_p, fw2, fb2, nullptr, out, M2, OUTF, HFd, 16);
}

// round 2
// speedup vs baseline: 1.0018x; 1.0018x over previous
#include <cuda_runtime.h>
#include <cub/cub.cuh>

#define Bb   32
#define Nn   2048
#define Ff   1024
#define HSd  8192
#define HFd  4096
#define OUTF 1024
#define M1   (Bb * Ff)   // 32768 rows for sorted-MLP (K = Nn)
#define M2   (Bb * Nn)   // 65536 rows for feature-MLP (K = Ff)

// ---------------- static device scratch (no allocations allowed) ----------------
__device__ float g_big[268435456]; // 1 GiB: h (M1 x HSd), reused as h2 (M2 x HFd)
__device__ float g_xt [67108864];  // xt [B,F,N], reused as y_s
__device__ float g_xs [67108864];  // xs [B,F,N], reused as yg
__device__ int   g_p  [67108864];  // permutation p [B,F,N]

// ---------------- transpose: x[B,N,F] -> xt[B,F,N] ----------------
__global__ void transpose_kernel(const float* __restrict__ x, float* __restrict__ xt) {
    __shared__ float tile[32][33];
    int b  = blockIdx.z;
    int n0 = blockIdx.y * 32;
    int f0 = blockIdx.x * 32;
    int tx = threadIdx.x, ty = threadIdx.y; // block (32, 8)
    const float* xb  = x  + (long)b * Nn * Ff;
    float*       xtb = xt + (long)b * Ff * Nn;
#pragma unroll
    for (int i = 0; i < 32; i += 8)
        tile[ty + i][tx] = xb[(long)(n0 + ty + i) * Ff + f0 + tx];
    __syncthreads();
#pragma unroll
    for (int i = 0; i < 32; i += 8)
        xtb[(long)(f0 + ty + i) * Nn + n0 + tx] = tile[tx][ty + i];
}

// ---------------- per-row stable argsort (radix) ----------------
// Produces p = argsort(row) and xs with xs[j] = row[rank(j)]  (== torch scatter(-1, p, row))
__global__ void __launch_bounds__(512) sort_kernel(const float* __restrict__ xt,
                                                   float* __restrict__ xs,
                                                   int* __restrict__ p) {
    typedef cub::BlockRadixSort<unsigned int, 512, 4, int> BRS;
    __shared__ typename BRS::TempStorage ts;
    __shared__ float rowv[Nn];
    __shared__ int   inv[Nn];

    long row = blockIdx.x;
    const float* in = xt + row * Nn;

    float4 v4 = reinterpret_cast<const float4*>(in)[threadIdx.x];
    float vj[4] = {v4.x, v4.y, v4.z, v4.w};

    unsigned keys[4]; int vals[4];
#pragma unroll
    for (int j = 0; j < 4; ++j) {
        int idx = threadIdx.x * 4 + j;
        rowv[idx] = vj[j];
        unsigned u = __float_as_uint(vj[j]);
        u = (u & 0x80000000u) ? ~u : (u | 0x80000000u); // order-preserving key transform
        keys[j] = u; vals[j] = idx;
    }
    __syncthreads();
    BRS(ts).Sort(keys, vals); // stable ascending -> matches jnp.argsort incl. ties
    __syncthreads();

    int4 pv;
    pv.x = vals[0]; pv.y = vals[1]; pv.z = vals[2]; pv.w = vals[3];
    reinterpret_cast<int4*>(p + row * Nn)[threadIdx.x] = pv;
#pragma unroll
    for (int j = 0; j < 4; ++j)
        inv[vals[j]] = threadIdx.x * 4 + j; // inv = rank
    __syncthreads();

    float4 o;
    o.x = rowv[inv[threadIdx.x * 4 + 0]];
    o.y = rowv[inv[threadIdx.x * 4 + 1]];
    o.z = rowv[inv[threadIdx.x * 4 + 2]];
    o.w = rowv[inv[threadIdx.x * 4 + 3]];
    reinterpret_cast<float4*>(xs + row * Nn)[threadIdx.x] = o;
}

// ---------------- per-row gather: yg[row, n] = y_s[row, p[row, n]] ----------------
__global__ void gather_kernel(const float* __restrict__ ys, const int* __restrict__ p,
                              float* __restrict__ yg) {
    __shared__ float sm[Nn];
    long row = blockIdx.x;
    for (int i = threadIdx.x; i < Nn; i += blockDim.x)
        sm[i] = ys[row * Nn + i];
    __syncthreads();
    for (int i = threadIdx.x; i < Nn; i += blockDim.x)
        yg[row * Nn + i] = sm[p[row * Nn + i]];
}

// ---------------- SIMT GEMM: C[M,Nc] = epi(A @ W^T + bias (+skip)) ----------------
// A row-major [M,K] (or, if ACOL, batched column-major: A[m,k] = buf[(m>>11)*K*2048 + k*2048 + (m&2047)])
// W row-major [Nc,K] (torch Linear weight). 128x128 tile, BK=16, 8x8 per thread.
// Supertiling: m-fastest within superM-column -> A panels + W stay L2-resident.
template<bool ACOL, bool RELU, bool SKIP>
__global__ void __launch_bounds__(256, 2) gemm128(
    const float* __restrict__ A, const float* __restrict__ W,
    const float* __restrict__ bias, const float* __restrict__ skip,
    float* __restrict__ C, int M, int Nc, int K, int superM)
{
    __shared__ float As[16][128];
    __shared__ float Bs[16][128];
    const int nTN = Nc >> 7;
    int tilesPer = superM * nTN;
    int sid = blockIdx.x / tilesPer;
    int rem = blockIdx.x - sid * tilesPer;
    int mt  = sid * superM + (rem % superM);
    int nt  = rem / superM;
    int m0 = mt << 7, n0 = nt << 7;

    int t  = threadIdx.x;
    int tx = t & 15, ty = t >> 4;

    float acc[8][8];
#pragma unroll
    for (int i = 0; i < 8; ++i)
#pragma unroll
        for (int j = 0; j < 8; ++j) acc[i][j] = 0.f;

    const float* Wt = W + (long)n0 * K;
    long abase = 0;
    if (ACOL) abase = (long)(m0 >> 11) * ((long)K * 2048) + (m0 & 2047);

    for (int k0 = 0; k0 < K; k0 += 16) {
#pragma unroll
        for (int q = 0; q < 2; ++q) {
            int idx = t + q * 256;
            int r = idx >> 2, c4 = idx & 3;
            if (!ACOL) {
                float4 v = *(const float4*)(A + (long)(m0 + r) * K + k0 + c4 * 4);
                As[c4 * 4 + 0][r] = v.x; As[c4 * 4 + 1][r] = v.y;
                As[c4 * 4 + 2][r] = v.z; As[c4 * 4 + 3][r] = v.w;
            } else {
                int kk = idx >> 5, mq = idx & 31;
                float4 v = *(const float4*)(A + abase + (long)(k0 + kk) * 2048 + mq * 4);
                *(float4*)&As[kk][mq * 4] = v;
            }
            float4 w = *(const float4*)(Wt + (long)r * K + k0 + c4 * 4);
            Bs[c4 * 4 + 0][r] = w.x; Bs[c4 * 4 + 1][r] = w.y;
            Bs[c4 * 4 + 2][r] = w.z; Bs[c4 * 4 + 3][r] = w.w;
        }
        __syncthreads();
#pragma unroll
        for (int kk = 0; kk < 16; ++kk) {
            float a[8], b[8];
            *(float4*)&a[0] = *(const float4*)&As[kk][ty * 8];
            *(float4*)&a[4] = *(const float4*)&As[kk][ty * 8 + 4];
            *(float4*)&b[0] = *(const float4*)&Bs[kk][tx * 8];
            *(float4*)&b[4] = *(const float4*)&Bs[kk][tx * 8 + 4];
#pragma unroll
            for (int i = 0; i < 8; ++i)
#pragma unroll
                for (int j = 0; j < 8; ++j)
                    acc[i][j] = fmaf(a[i], b[j], acc[i][j]);
        }
        __syncthreads();
    }

    float bi[8];
#pragma unroll
    for (int j = 0; j < 8; ++j) bi[j] = bias[n0 + tx * 8 + j];
#pragma unroll
    for (int i = 0; i < 8; ++i) {
        long off = (long)(m0 + ty * 8 + i) * Nc + n0 + tx * 8;
        float outv[8];
#pragma unroll
        for (int j = 0; j < 8; ++j) {
            float v = acc[i][j] + bi[j];
            if (SKIP) v += skip[off + j];
            if (RELU) v = fmaxf(v, 0.f);
            outv[j] = v;
        }
        *(float4*)(C + off)     = *(float4*)&outv[0];
        *(float4*)(C + off + 4) = *(float4*)&outv[4];
    }
}

// ---------------- launch ----------------
extern "C" void kernel_launch(void* const* d_in, const int* in_sizes, int n_in,
                              void* d_out, int out_size) {
    const float* x   = (const float*)d_in[0];
    const float* sw1 = (const float*)d_in[1];
    const float* sb1 = (const float*)d_in[2];
    const float* sw2 = (const float*)d_in[3];
    const float* sb2 = (const float*)d_in[4];
    const float* fw1 = (const float*)d_in[5];
    const float* fb1 = (const float*)d_in[6];
    const float* fw2 = (const float*)d_in[7];
    const float* fb2 = (const float*)d_in[8];
    float* out = (float*)d_out;

    float *xt_p, *xs_p, *big_p; int *p_p;
    cudaGetSymbolAddress((void**)&xt_p,  g_xt);
    cudaGetSymbolAddress((void**)&xs_p,  g_xs);
    cudaGetSymbolAddress((void**)&big_p, g_big);
    cudaGetSymbolAddress((void**)&p_p,   g_p);

    // 1) transpose x -> xt[B,F,N]
    dim3 tb(32, 8), tg(Ff / 32, Nn / 32, Bb);
    transpose_kernel<<<tg, tb>>>(x, xt_p);

    // 2) per-row sort: xs (permuted values) + p (argsort)
    sort_kernel<<<M1, 512>>>(xt_p, xs_p, p_p);

    // 3) h = relu(xs @ sw1^T + sb1)            [M1, HSd]
    gemm128<false, true, false><<<(M1 / 128) * (HSd / 128), 256>>>(
        xs_p, sw1, sb1, nullptr, big_p, M1, HSd, Nn, 32);

    // 4) y_s = h @ sw2^T + sb2 + xs            [M1, Nn]  (into xt buffer)
    gemm128<false, false, true><<<(M1 / 128) * (Nn / 128), 256>>>(
        big_p, sw2, sb2, xs_p, xt_p, M1, Nn, HSd, 8);

    // 5) yg[row, n] = y_s[row, p[row, n]]      [B,F,N]   (into xs buffer)
    gather_kernel<<<M1, 256>>>(xt_p, p_p, xs_p);

    // 6) h2 = relu(yt @ fw1^T + fb1), yt[b,n,f] = yg[b,f,n] read column-major (no transpose)
    gemm128<true, true, false><<<(M2 / 128) * (HFd / 128), 256>>>(
        xs_p, fw1, fb1, nullptr, big_p, M2, HFd, Ff, 64);

    // 7) out = h2 @ fw2^T + fb2                [B,N,OUT]
    gemm128<false, false, false><<<(M2 / 128) * (OUTF / 128), 256>>>(
        big_p, fw2, fb2, nullptr, out, M2, OUTF, HFd, 16);
}

// round 7
// speedup vs baseline: 2.8486x; 2.8435x over previous
#include <cuda_runtime.h>
#include <cub/cub.cuh>
#include <cstdint>

#define Bb   32
#define Nn   2048
#define Ff   1024
#define HSd  8192
#define HFd  4096
#define OUTF 1024
#define M1   (Bb * Ff)   // 32768 rows for sorted-MLP (K = Nn)
#define M2   (Bb * Nn)   // 65536 rows for feature-MLP (K = Ff)

// ---------------- static device scratch ----------------
__device__ float g_big[268435456]; // 1 GiB: h (M1 x HSd), reused as h2 (M2 x HFd)
__device__ float g_xt [67108864];  // xt [B,F,N], reused as y_s
__device__ float g_xs [67108864];  // xs [B,F,N], reused as yg
__device__ float g_yt [67108864];  // yt [B,N,F]
__device__ int   g_p  [67108864];  // permutation p [B,F,N]

// ================= PTX helpers (plain sm_103 — NO 'a' features) =================
__device__ __forceinline__ uint32_t smem_u32(const void* p) {
    uint32_t a;
    asm("{ .reg .u64 t; cvta.to.shared.u64 t, %1; cvt.u32.u64 %0, t; }" : "=r"(a) : "l"(p));
    return a;
}

#define CP_ASYNC16(s, g) \
    asm volatile("cp.async.cg.shared.global [%0], [%1], 16;\n" :: "r"(s), "l"(g) : "memory")
#define CP_COMMIT() asm volatile("cp.async.commit_group;\n" ::: "memory")
#define CP_WAIT2()  asm volatile("cp.async.wait_group 2;\n" ::: "memory")

__device__ __forceinline__ uint32_t f2tf(float f) {
    uint32_t r;
    asm("cvt.rna.tf32.f32 %0, %1;" : "=r"(r) : "f"(f));
    return r;
}

__device__ __forceinline__ void mma_tf32(float& d0, float& d1, float& d2, float& d3,
                                         uint32_t a0, uint32_t a1, uint32_t a2, uint32_t a3,
                                         uint32_t b0, uint32_t b1) {
    asm volatile("mma.sync.aligned.m16n8k8.row.col.f32.tf32.tf32.f32 "
                 "{%0,%1,%2,%3}, {%4,%5,%6,%7}, {%8,%9}, {%0,%1,%2,%3};"
                 : "+f"(d0), "+f"(d1), "+f"(d2), "+f"(d3)
                 : "r"(a0), "r"(a1), "r"(a2), "r"(a3), "r"(b0), "r"(b1));
}

// ================= tf32 mma.sync GEMM =================
// C[M,Nc] = epi(A @ W^T + bias (+skip)); A row-major [M,K], W row-major [Nc,K].
// CTA 128x128, BK=32, 4-stage cp.async, 256 thr = 2(m) x 4(n) warps, warp tile 64x32.
#define TM 128
#define TN 128
#define BK 32
#define LDA 36                              // smem row stride (floats): bank-conflict-free
#define TILE_FLOATS (128 * LDA)             // 4608 floats = 18432 B per matrix
#define STAGE_FLOATS (2 * TILE_FLOATS)      // A then B
#define SM_BIAS_F 0                         // 128 floats
#define SM_STG0_F 256                       // 1 KiB aligned-ish start
#define GEMM_SMEM ((SM_STG0_F + 4 * STAGE_FLOATS) * 4)  // 148480 B

template<bool RELU, bool SKIP>
__global__ void __launch_bounds__(256, 1) gemm_mma(
    const float* __restrict__ A, const float* __restrict__ W,
    const float* __restrict__ bias, const float* __restrict__ skip,
    float* __restrict__ C, int M, int Nc, int K, int superM)
{
    extern __shared__ float smem[];
    uint32_t sb = smem_u32(smem);
    int tid = threadIdx.x, wid = tid >> 5, lane = tid & 31;
    int wm = wid & 1, wn = wid >> 1;        // warp grid 2 x 4
    int gq = lane >> 2, lq = lane & 3;      // group-of-4 id, id-in-group

    // supertiled raster (m-fastest within superM column chunk)
    const int nTN = Nc / TN;
    int tilesPer = superM * nTN;
    int sid = blockIdx.x / tilesPer;
    int rem = blockIdx.x - sid * tilesPer;
    int mt  = sid * superM + (rem % superM);
    int nt  = rem / superM;
    int m0 = mt * TM, n0 = nt * TN;

    for (int i = tid; i < TN; i += 256) smem[SM_BIAS_F + i] = bias[n0 + i];

    // cp.async mapping: idx in [0,1024): row = idx>>3, 16B chunk = idx&7
    int r0 = tid >> 3, ch = tid & 7;
    const char* gA = (const char*)(A + (long)(m0 + r0) * K) + ch * 16;
    const char* gB = (const char*)(W + (long)(n0 + r0) * K) + ch * 16;
    long rowStep = (long)32 * K * 4;                // +32 rows (q step), bytes
    uint32_t sOffA = (uint32_t)(r0 * (LDA * 4) + ch * 16);  // + q*32*LDA*4
    int KS = K / BK;

#define LOAD_STAGE(s_, kblk_) do { \
        uint32_t sa_ = sb + (SM_STG0_F + (s_) * STAGE_FLOATS) * 4; \
        uint32_t sbm_ = sa_ + TILE_FLOATS * 4; \
        const char* pa_ = gA + (long)(kblk_) * 128; \
        const char* pb_ = gB + (long)(kblk_) * 128; \
        _Pragma("unroll") \
        for (int q = 0; q < 4; ++q) \
            CP_ASYNC16(sa_ + sOffA + q * (32 * LDA * 4), pa_ + q * rowStep); \
        _Pragma("unroll") \
        for (int q = 0; q < 4; ++q) \
            CP_ASYNC16(sbm_ + sOffA + q * (32 * LDA * 4), pb_ + q * rowStep); \
    } while (0)

    // prologue: stages 0..2
    for (int s = 0; s < 3; ++s) { LOAD_STAGE(s, s); CP_COMMIT(); }

    float acc[4][4][4];
#pragma unroll
    for (int i = 0; i < 4; ++i)
#pragma unroll
        for (int j = 0; j < 4; ++j) {
            acc[i][j][0] = 0.f; acc[i][j][1] = 0.f;
            acc[i][j][2] = 0.f; acc[i][j][3] = 0.f;
        }

    for (int i = 0; i < KS; ++i) {
        CP_WAIT2();
        __syncthreads();
        int j = i + 3;
        if (j < KS) LOAD_STAGE(j & 3, j);
        CP_COMMIT();

        const float* sA = smem + SM_STG0_F + (i & 3) * STAGE_FLOATS;
        const float* sB = sA + TILE_FLOATS;
#pragma unroll
        for (int kk = 0; kk < 4; ++kk) {
            int kb = kk * 8;
            uint32_t af[4][4];
#pragma unroll
            for (int mf = 0; mf < 4; ++mf) {
                int r = wm * 64 + mf * 16 + gq;
                int c = kb + lq;
                af[mf][0] = f2tf(sA[r * LDA + c]);
                af[mf][1] = f2tf(sA[(r + 8) * LDA + c]);
                af[mf][2] = f2tf(sA[r * LDA + c + 4]);
                af[mf][3] = f2tf(sA[(r + 8) * LDA + c + 4]);
            }
            uint32_t bf[4][2];
#pragma unroll
            for (int nf = 0; nf < 4; ++nf) {
                int n = wn * 32 + nf * 8 + gq;
                bf[nf][0] = f2tf(sB[n * LDA + kb + lq]);
                bf[nf][1] = f2tf(sB[n * LDA + kb + lq + 4]);
            }
#pragma unroll
            for (int mf = 0; mf < 4; ++mf)
#pragma unroll
                for (int nf = 0; nf < 4; ++nf)
                    mma_tf32(acc[mf][nf][0], acc[mf][nf][1], acc[mf][nf][2], acc[mf][nf][3],
                             af[mf][0], af[mf][1], af[mf][2], af[mf][3],
                             bf[nf][0], bf[nf][1]);
        }
    }

    // epilogue from registers
#pragma unroll
    for (int mf = 0; mf < 4; ++mf) {
        int ra = m0 + wm * 64 + mf * 16 + gq;
#pragma unroll
        for (int nf = 0; nf < 4; ++nf) {
            int cl = wn * 32 + nf * 8 + 2 * lq;      // local col
            long c0off = (long)ra * Nc + n0 + cl;
            long c1off = (long)(ra + 8) * Nc + n0 + cl;
            float b0 = smem[SM_BIAS_F + cl], b1 = smem[SM_BIAS_F + cl + 1];
            float2 o0, o1;
            o0.x = acc[mf][nf][0] + b0; o0.y = acc[mf][nf][1] + b1;
            o1.x = acc[mf][nf][2] + b0; o1.y = acc[mf][nf][3] + b1;
            if (SKIP) {
                float2 s0 = *(const float2*)(skip + c0off);
                float2 s1 = *(const float2*)(skip + c1off);
                o0.x += s0.x; o0.y += s0.y; o1.x += s1.x; o1.y += s1.y;
            }
            if (RELU) {
                o0.x = fmaxf(o0.x, 0.f); o0.y = fmaxf(o0.y, 0.f);
                o1.x = fmaxf(o1.x, 0.f); o1.y = fmaxf(o1.y, 0.f);
            }
            *(float2*)(C + c0off) = o0;
            *(float2*)(C + c1off) = o1;
        }
    }
#undef LOAD_STAGE
}

// ---------------- transpose: in[B,R,C] -> out[B,C,R] ----------------
template<int R, int C>
__global__ void transpose_t(const float* __restrict__ in, float* __restrict__ out) {
    __shared__ float tile[32][33];
    int b  = blockIdx.z;
    int r0 = blockIdx.y * 32;
    int c0 = blockIdx.x * 32;
    int tx = threadIdx.x, ty = threadIdx.y;  // (32, 8)
    const float* ib = in  + (long)b * R * C;
    float*       ob = out + (long)b * R * C;
#pragma unroll
    for (int i = 0; i < 32; i += 8)
        tile[ty + i][tx] = ib[(long)(r0 + ty + i) * C + c0 + tx];
    __syncthreads();
#pragma unroll
    for (int i = 0; i < 32; i += 8)
        ob[(long)(c0 + ty + i) * R + r0 + tx] = tile[tx][ty + i];
}

// ---------------- per-row stable argsort (radix) ----------------
__global__ void __launch_bounds__(512) sort_kernel(const float* __restrict__ xt,
                                                   float* __restrict__ xs,
                                                   int* __restrict__ p) {
    typedef cub::BlockRadixSort<unsigned int, 512, 4, int> BRS;
    __shared__ typename BRS::TempStorage ts;
    __shared__ float rowv[Nn];
    __shared__ int   inv[Nn];

    long row = blockIdx.x;
    const float* in = xt + row * Nn;

    float4 v4 = reinterpret_cast<const float4*>(in)[threadIdx.x];
    float vj[4] = {v4.x, v4.y, v4.z, v4.w};

    unsigned keys[4]; int vals[4];
#pragma unroll
    for (int j = 0; j < 4; ++j) {
        int idx = threadIdx.x * 4 + j;
        rowv[idx] = vj[j];
        unsigned u = __float_as_uint(vj[j]);
        u = (u & 0x80000000u) ? ~u : (u | 0x80000000u);
        keys[j] = u; vals[j] = idx;
    }
    __syncthreads();
    BRS(ts).Sort(keys, vals);
    __syncthreads();

    int4 pv;
    pv.x = vals[0]; pv.y = vals[1]; pv.z = vals[2]; pv.w = vals[3];
    reinterpret_cast<int4*>(p + row * Nn)[threadIdx.x] = pv;
#pragma unroll
    for (int j = 0; j < 4; ++j)
        inv[vals[j]] = threadIdx.x * 4 + j;
    __syncthreads();

    float4 o;
    o.x = rowv[inv[threadIdx.x * 4 + 0]];
    o.y = rowv[inv[threadIdx.x * 4 + 1]];
    o.z = rowv[inv[threadIdx.x * 4 + 2]];
    o.w = rowv[inv[threadIdx.x * 4 + 3]];
    reinterpret_cast<float4*>(xs + row * Nn)[threadIdx.x] = o;
}

// ---------------- per-row gather: yg[row, n] = y_s[row, p[row, n]] ----------------
__global__ void gather_kernel(const float* __restrict__ ys, const int* __restrict__ p,
                              float* __restrict__ yg) {
    __shared__ float sm[Nn];
    long row = blockIdx.x;
    for (int i = threadIdx.x; i < Nn; i += blockDim.x)
        sm[i] = ys[row * Nn + i];
    __syncthreads();
    for (int i = threadIdx.x; i < Nn; i += blockDim.x)
        yg[row * Nn + i] = sm[p[row * Nn + i]];
}

// ---------------- launch ----------------
extern "C" void kernel_launch(void* const* d_in, const int* in_sizes, int n_in,
                              void* d_out, int out_size) {
    const float* x   = (const float*)d_in[0];
    const float* sw1 = (const float*)d_in[1];
    const float* sb1 = (const float*)d_in[2];
    const float* sw2 = (const float*)d_in[3];
    const float* sb2 = (const float*)d_in[4];
    const float* fw1 = (const float*)d_in[5];
    const float* fb1 = (const float*)d_in[6];
    const float* fw2 = (const float*)d_in[7];
    const float* fb2 = (const float*)d_in[8];
    float* out = (float*)d_out;

    float *xt_p, *xs_p, *yt_p, *big_p; int *p_p;
    cudaGetSymbolAddress((void**)&xt_p,  g_xt);
    cudaGetSymbolAddress((void**)&xs_p,  g_xs);
    cudaGetSymbolAddress((void**)&yt_p,  g_yt);
    cudaGetSymbolAddress((void**)&big_p, g_big);
    cudaGetSymbolAddress((void**)&p_p,   g_p);

    cudaFuncSetAttribute(gemm_mma<true,  false>, cudaFuncAttributeMaxDynamicSharedMemorySize, GEMM_SMEM);
    cudaFuncSetAttribute(gemm_mma<false, true >, cudaFuncAttributeMaxDynamicSharedMemorySize, GEMM_SMEM);
    cudaFuncSetAttribute(gemm_mma<false, false>, cudaFuncAttributeMaxDynamicSharedMemorySize, GEMM_SMEM);

    dim3 tb(32, 8);

    // 1) transpose x[B,N,F] -> xt[B,F,N]
    transpose_t<Nn, Ff><<<dim3(Ff / 32, Nn / 32, Bb), tb>>>(x, xt_p);

    // 2) per-row sort: xs (permuted values) + p (argsort)
    sort_kernel<<<M1, 512>>>(xt_p, xs_p, p_p);

    // 3) h = relu(xs @ sw1^T + sb1)            [M1, HSd]
    gemm_mma<true, false><<<(M1 / TM) * (HSd / TN), 256, GEMM_SMEM>>>(
        xs_p, sw1, sb1, nullptr, big_p, M1, HSd, Nn, 16);

    // 4) y_s = h @ sw2^T + sb2 + xs            [M1, Nn]  (into xt buffer)
    gemm_mma<false, true><<<(M1 / TM) * (Nn / TN), 256, GEMM_SMEM>>>(
        big_p, sw2, sb2, xs_p, xt_p, M1, Nn, HSd, 16);

    // 5) yg[row, n] = y_s[row, p[row, n]]      [B,F,N]   (into xs buffer)
    gather_kernel<<<M1, 256>>>(xt_p, p_p, xs_p);

    // 6) transpose yg[B,F,N] -> yt[B,N,F]
    transpose_t<Ff, Nn><<<dim3(Nn / 32, Ff / 32, Bb), tb>>>(xs_p, yt_p);

    // 7) h2 = relu(yt @ fw1^T + fb1)           [M2, HFd]
    gemm_mma<true, false><<<(M2 / TM) * (HFd / TN), 256, GEMM_SMEM>>>(
        yt_p, fw1, fb1, nullptr, big_p, M2, HFd, Ff, 16);

    // 8) out = h2 @ fw2^T + fb2                [B,N,OUT]
    gemm_mma<false, false><<<(M2 / TM) * (OUTF / TN), 256, GEMM_SMEM>>>(
        big_p, fw2, fb2, nullptr, out, M2, OUTF, HFd, 32);
}

// round 9
// speedup vs baseline: 3.5922x; 1.2611x over previous
#include <cuda_runtime.h>
#include <cub/cub.cuh>
#include <cstdint>

#define Bb   32
#define Nn   2048
#define Ff   1024
#define HSd  8192
#define HFd  4096
#define OUTF 1024
#define M1   (Bb * Ff)   // 32768 rows for sorted-MLP (K = Nn)
#define M2   (Bb * Nn)   // 65536 rows for feature-MLP (K = Ff)

// ---------------- static device scratch ----------------
__device__ float g_big[268435456]; // 1 GiB: h (M1 x HSd), reused as h2 (M2 x HFd)
__device__ float g_xt [67108864];  // xt [B,F,N], reused as y_s
__device__ float g_xs [67108864];  // xs [B,F,N] (tf32-rounded), reused as yg
__device__ float g_yt [67108864];  // yt [B,N,F] (tf32-rounded)
__device__ int   g_p  [67108864];  // permutation p [B,F,N]
__device__ float g_wts[41943040];  // tf32-rounded weights: sw1|sw2|fw1|fw2

#define OFF_SW1 0
#define OFF_SW2 16777216
#define OFF_FW1 33554432
#define OFF_FW2 37748736

// ================= PTX helpers (plain sm_103 — NO 'a' features) =================
__device__ __forceinline__ uint32_t smem_u32(const void* p) {
    uint32_t a;
    asm("{ .reg .u64 t; cvta.to.shared.u64 t, %1; cvt.u32.u64 %0, t; }" : "=r"(a) : "l"(p));
    return a;
}

#define CP_ASYNC16(s, g) \
    asm volatile("cp.async.cg.shared.global [%0], [%1], 16;\n" :: "r"(s), "l"(g) : "memory")
#define CP_COMMIT() asm volatile("cp.async.commit_group;\n" ::: "memory")
#define CP_WAIT1()  asm volatile("cp.async.wait_group 1;\n" ::: "memory")

__device__ __forceinline__ float f2tf_f(float f) {
    uint32_t r;
    asm("cvt.rna.tf32.f32 %0, %1;" : "=r"(r) : "f"(f));
    return __uint_as_float(r);
}

__device__ __forceinline__ void mma_tf32(float& d0, float& d1, float& d2, float& d3,
                                         uint32_t a0, uint32_t a1, uint32_t a2, uint32_t a3,
                                         uint32_t b0, uint32_t b1) {
    asm volatile("mma.sync.aligned.m16n8k8.row.col.f32.tf32.tf32.f32 "
                 "{%0,%1,%2,%3}, {%4,%5,%6,%7}, {%8,%9}, {%0,%1,%2,%3};"
                 : "+f"(d0), "+f"(d1), "+f"(d2), "+f"(d3)
                 : "r"(a0), "r"(a1), "r"(a2), "r"(a3), "r"(b0), "r"(b1));
}

// ---------------- weight pre-round: dst = tf32_round(src) ----------------
__global__ void round_copy(const float* __restrict__ src, float* __restrict__ dst, int n4) {
    int i = blockIdx.x * blockDim.x + threadIdx.x;
    if (i < n4) {
        float4 v = ((const float4*)src)[i];
        v.x = f2tf_f(v.x); v.y = f2tf_f(v.y); v.z = f2tf_f(v.z); v.w = f2tf_f(v.w);
        ((float4*)dst)[i] = v;
    }
}

// ================= tf32 mma.sync GEMM =================
// C[M,Nc] = epi(A @ W^T + bias (+skip)); A row-major [M,K] (pre-rounded to tf32),
// W row-major [Nc,K] (pre-rounded). CTA 128x128, BK=32, 3-stage cp.async,
// 256 thr = 2(m) x 4(n) warps, warp tile 64x32, 2 CTAs/SM.
#define TM 128
#define TN 128
#define BK 32
#define LDA 36                              // smem row stride (floats): bank-conflict-free
#define TILE_FLOATS (128 * LDA)             // 4608 floats = 18432 B per matrix
#define STAGE_FLOATS (2 * TILE_FLOATS)      // A then B
#define SM_BIAS_F 0                         // 128 floats
#define SM_STG0_F 256
#define GEMM_SMEM ((SM_STG0_F + 3 * STAGE_FLOATS) * 4)  // 111616 B

template<bool RELU, bool SKIP, bool ROUND>
__global__ void __launch_bounds__(256, 2) gemm_mma(
    const float* __restrict__ A, const float* __restrict__ W,
    const float* __restrict__ bias, const float* __restrict__ skip,
    float* __restrict__ C, int M, int Nc, int K, int superM)
{
    extern __shared__ float smem[];
    uint32_t sb = smem_u32(smem);
    int tid = threadIdx.x, wid = tid >> 5, lane = tid & 31;
    int wm = wid & 1, wn = wid >> 1;        // warp grid 2 x 4
    int gq = lane >> 2, lq = lane & 3;      // group-of-4 id, id-in-group

    // supertiled raster (m-fastest within superM column chunk)
    const int nTN = Nc / TN;
    int tilesPer = superM * nTN;
    int sid = blockIdx.x / tilesPer;
    int rem = blockIdx.x - sid * tilesPer;
    int mt  = sid * superM + (rem % superM);
    int nt  = rem / superM;
    int m0 = mt * TM, n0 = nt * TN;

    for (int i = tid; i < TN; i += 256) smem[SM_BIAS_F + i] = bias[n0 + i];

    // cp.async mapping: idx in [0,1024): row = idx>>3, 16B chunk = idx&7
    int r0 = tid >> 3, ch = tid & 7;
    const char* gA = (const char*)(A + (long)(m0 + r0) * K) + ch * 16;
    const char* gB = (const char*)(W + (long)(n0 + r0) * K) + ch * 16;
    long rowStep = (long)32 * K * 4;                // +32 rows (q step), bytes
    uint32_t sOffA = (uint32_t)(r0 * (LDA * 4) + ch * 16);
    int KS = K / BK;

#define LOAD_STAGE(s_, kblk_) do { \
        uint32_t sa_ = sb + (SM_STG0_F + (s_) * STAGE_FLOATS) * 4; \
        uint32_t sbm_ = sa_ + TILE_FLOATS * 4; \
        const char* pa_ = gA + (long)(kblk_) * 128; \
        const char* pb_ = gB + (long)(kblk_) * 128; \
        _Pragma("unroll") \
        for (int q = 0; q < 4; ++q) \
            CP_ASYNC16(sa_ + sOffA + q * (32 * LDA * 4), pa_ + q * rowStep); \
        _Pragma("unroll") \
        for (int q = 0; q < 4; ++q) \
            CP_ASYNC16(sbm_ + sOffA + q * (32 * LDA * 4), pb_ + q * rowStep); \
    } while (0)

    // prologue: stages 0..1
    LOAD_STAGE(0, 0); CP_COMMIT();
    LOAD_STAGE(1, 1); CP_COMMIT();

    float acc[4][4][4];
#pragma unroll
    for (int i = 0; i < 4; ++i)
#pragma unroll
        for (int j = 0; j < 4; ++j) {
            acc[i][j][0] = 0.f; acc[i][j][1] = 0.f;
            acc[i][j][2] = 0.f; acc[i][j][3] = 0.f;
        }

    // per-warp fragment base rows precomputed
    int aRow = wm * 64 + gq;       // + mf*16 (+8)
    int bRow = wn * 32 + gq;       // + nf*8

    int stg = 0;
    for (int i = 0; i < KS; ++i) {
        CP_WAIT1();
        __syncthreads();
        int j = i + 2;
        if (j < KS) {
            int sn = stg + 2; if (sn >= 3) sn -= 3;
            LOAD_STAGE(sn, j);
        }
        CP_COMMIT();

        const uint32_t* sA = (const uint32_t*)(smem + SM_STG0_F + stg * STAGE_FLOATS);
        const uint32_t* sB = sA + TILE_FLOATS;
#pragma unroll
        for (int kk = 0; kk < 4; ++kk) {
            int kb = kk * 8 + lq;
            uint32_t af[4][4];
#pragma unroll
            for (int mf = 0; mf < 4; ++mf) {
                int r = aRow + mf * 16;
                af[mf][0] = sA[r * LDA + kb];
                af[mf][1] = sA[(r + 8) * LDA + kb];
                af[mf][2] = sA[r * LDA + kb + 4];
                af[mf][3] = sA[(r + 8) * LDA + kb + 4];
            }
            uint32_t bf[4][2];
#pragma unroll
            for (int nf = 0; nf < 4; ++nf) {
                int n = bRow + nf * 8;
                bf[nf][0] = sB[n * LDA + kb];
                bf[nf][1] = sB[n * LDA + kb + 4];
            }
#pragma unroll
            for (int mf = 0; mf < 4; ++mf)
#pragma unroll
                for (int nf = 0; nf < 4; ++nf)
                    mma_tf32(acc[mf][nf][0], acc[mf][nf][1], acc[mf][nf][2], acc[mf][nf][3],
                             af[mf][0], af[mf][1], af[mf][2], af[mf][3],
                             bf[nf][0], bf[nf][1]);
        }
        ++stg; if (stg == 3) stg = 0;
    }

    // epilogue from registers
#pragma unroll
    for (int mf = 0; mf < 4; ++mf) {
        int ra = m0 + wm * 64 + mf * 16 + gq;
#pragma unroll
        for (int nf = 0; nf < 4; ++nf) {
            int cl = wn * 32 + nf * 8 + 2 * lq;      // local col
            long c0off = (long)ra * Nc + n0 + cl;
            long c1off = (long)(ra + 8) * Nc + n0 + cl;
            float b0 = smem[SM_BIAS_F + cl], b1 = smem[SM_BIAS_F + cl + 1];
            float2 o0, o1;
            o0.x = acc[mf][nf][0] + b0; o0.y = acc[mf][nf][1] + b1;
            o1.x = acc[mf][nf][2] + b0; o1.y = acc[mf][nf][3] + b1;
            if (SKIP) {
                float2 s0 = *(const float2*)(skip + c0off);
                float2 s1 = *(const float2*)(skip + c1off);
                o0.x += s0.x; o0.y += s0.y; o1.x += s1.x; o1.y += s1.y;
            }
            if (RELU) {
                o0.x = fmaxf(o0.x, 0.f); o0.y = fmaxf(o0.y, 0.f);
                o1.x = fmaxf(o1.x, 0.f); o1.y = fmaxf(o1.y, 0.f);
            }
            if (ROUND) {
                o0.x = f2tf_f(o0.x); o0.y = f2tf_f(o0.y);
                o1.x = f2tf_f(o1.x); o1.y = f2tf_f(o1.y);
            }
            *(float2*)(C + c0off) = o0;
            *(float2*)(C + c1off) = o1;
        }
    }
#undef LOAD_STAGE
}

// ---------------- transpose: in[B,R,C] -> out[B,C,R] ----------------
template<int R, int C, bool ROUND>
__global__ void transpose_t(const float* __restrict__ in, float* __restrict__ out) {
    __shared__ float tile[32][33];
    int b  = blockIdx.z;
    int r0 = blockIdx.y * 32;
    int c0 = blockIdx.x * 32;
    int tx = threadIdx.x, ty = threadIdx.y;  // (32, 8)
    const float* ib = in  + (long)b * R * C;
    float*       ob = out + (long)b * R * C;
#pragma unroll
    for (int i = 0; i < 32; i += 8)
        tile[ty + i][tx] = ib[(long)(r0 + ty + i) * C + c0 + tx];
    __syncthreads();
#pragma unroll
    for (int i = 0; i < 32; i += 8) {
        float v = tile[tx][ty + i];
        if (ROUND) v = f2tf_f(v);
        ob[(long)(c0 + ty + i) * R + r0 + tx] = v;
    }
}

// ---------------- per-row stable argsort (radix); writes tf32-rounded xs ----------------
__global__ void __launch_bounds__(512) sort_kernel(const float* __restrict__ xt,
                                                   float* __restrict__ xs,
                                                   int* __restrict__ p) {
    typedef cub::BlockRadixSort<unsigned int, 512, 4, int> BRS;
    __shared__ typename BRS::TempStorage ts;
    __shared__ float rowv[Nn];
    __shared__ int   inv[Nn];

    long row = blockIdx.x;
    const float* in = xt + row * Nn;

    float4 v4 = reinterpret_cast<const float4*>(in)[threadIdx.x];
    float vj[4] = {v4.x, v4.y, v4.z, v4.w};

    unsigned keys[4]; int vals[4];
#pragma unroll
    for (int j = 0; j < 4; ++j) {
        int idx = threadIdx.x * 4 + j;
        rowv[idx] = vj[j];
        unsigned u = __float_as_uint(vj[j]);
        u = (u & 0x80000000u) ? ~u : (u | 0x80000000u);  // order-preserving
        keys[j] = u; vals[j] = idx;
    }
    __syncthreads();
    BRS(ts).Sort(keys, vals);  // stable ascending, exact keys -> p matches reference
    __syncthreads();

    int4 pv;
    pv.x = vals[0]; pv.y = vals[1]; pv.z = vals[2]; pv.w = vals[3];
    reinterpret_cast<int4*>(p + row * Nn)[threadIdx.x] = pv;
#pragma unroll
    for (int j = 0; j < 4; ++j)
        inv[vals[j]] = threadIdx.x * 4 + j;
    __syncthreads();

    float4 o;
    o.x = f2tf_f(rowv[inv[threadIdx.x * 4 + 0]]);
    o.y = f2tf_f(rowv[inv[threadIdx.x * 4 + 1]]);
    o.z = f2tf_f(rowv[inv[threadIdx.x * 4 + 2]]);
    o.w = f2tf_f(rowv[inv[threadIdx.x * 4 + 3]]);
    reinterpret_cast<float4*>(xs + row * Nn)[threadIdx.x] = o;
}

// ---------------- per-row gather: yg[row, n] = y_s[row, p[row, n]] ----------------
__global__ void gather_kernel(const float* __restrict__ ys, const int* __restrict__ p,
                              float* __restrict__ yg) {
    __shared__ float sm[Nn];
    long row = blockIdx.x;
    for (int i = threadIdx.x; i < Nn; i += blockDim.x)
        sm[i] = ys[row * Nn + i];
    __syncthreads();
    for (int i = threadIdx.x; i < Nn; i += blockDim.x)
        yg[row * Nn + i] = sm[p[row * Nn + i]];
}

// ---------------- launch ----------------
extern "C" void kernel_launch(void* const* d_in, const int* in_sizes, int n_in,
                              void* d_out, int out_size) {
    const float* x   = (const float*)d_in[0];
    const float* sw1 = (const float*)d_in[1];
    const float* sb1 = (const float*)d_in[2];
    const float* sw2 = (const float*)d_in[3];
    const float* sb2 = (const float*)d_in[4];
    const float* fw1 = (const float*)d_in[5];
    const float* fb1 = (const float*)d_in[6];
    const float* fw2 = (const float*)d_in[7];
    const float* fb2 = (const float*)d_in[8];
    float* out = (float*)d_out;

    float *xt_p, *xs_p, *yt_p, *big_p, *w_p; int *p_p;
    cudaGetSymbolAddress((void**)&xt_p,  g_xt);
    cudaGetSymbolAddress((void**)&xs_p,  g_xs);
    cudaGetSymbolAddress((void**)&yt_p,  g_yt);
    cudaGetSymbolAddress((void**)&big_p, g_big);
    cudaGetSymbolAddress((void**)&w_p,   g_wts);
    cudaGetSymbolAddress((void**)&p_p,   g_p);

    cudaFuncSetAttribute(gemm_mma<true,  false, true >, cudaFuncAttributeMaxDynamicSharedMemorySize, GEMM_SMEM);
    cudaFuncSetAttribute(gemm_mma<false, true,  false>, cudaFuncAttributeMaxDynamicSharedMemorySize, GEMM_SMEM);
    cudaFuncSetAttribute(gemm_mma<false, false, false>, cudaFuncAttributeMaxDynamicSharedMemorySize, GEMM_SMEM);

    dim3 tb(32, 8);

    // 0) pre-round weights to tf32 (into static scratch)
    round_copy<<<(HSd * Nn / 4 + 255) / 256, 256>>>(sw1, w_p + OFF_SW1, HSd * Nn / 4);
    round_copy<<<(Nn * HSd / 4 + 255) / 256, 256>>>(sw2, w_p + OFF_SW2, Nn * HSd / 4);
    round_copy<<<(HFd * Ff / 4 + 255) / 256, 256>>>(fw1, w_p + OFF_FW1, HFd * Ff / 4);
    round_copy<<<(OUTF * HFd / 4 + 255) / 256, 256>>>(fw2, w_p + OFF_FW2, OUTF * HFd / 4);

    // 1) transpose x[B,N,F] -> xt[B,F,N] (exact — sort keys must match reference)
    transpose_t<Nn, Ff, false><<<dim3(Ff / 32, Nn / 32, Bb), tb>>>(x, xt_p);

    // 2) per-row sort: xs (tf32-rounded permuted values) + p (argsort)
    sort_kernel<<<M1, 512>>>(xt_p, xs_p, p_p);

    // 3) h = tf32(relu(xs @ sw1^T + sb1))      [M1, HSd]
    gemm_mma<true, false, true><<<(M1 / TM) * (HSd / TN), 256, GEMM_SMEM>>>(
        xs_p, w_p + OFF_SW1, sb1, nullptr, big_p, M1, HSd, Nn, 16);

    // 4) y_s = h @ sw2^T + sb2 + xs            [M1, Nn]  (into xt buffer)
    gemm_mma<false, true, false><<<(M1 / TM) * (Nn / TN), 256, GEMM_SMEM>>>(
        big_p, w_p + OFF_SW2, sb2, xs_p, xt_p, M1, Nn, HSd, 16);

    // 5) yg[row, n] = y_s[row, p[row, n]]      [B,F,N]   (into xs buffer)
    gather_kernel<<<M1, 256>>>(xt_p, p_p, xs_p);

    // 6) transpose yg[B,F,N] -> yt[B,N,F], tf32-rounded
    transpose_t<Ff, Nn, true><<<dim3(Nn / 32, Ff / 32, Bb), tb>>>(xs_p, yt_p);

    // 7) h2 = tf32(relu(yt @ fw1^T + fb1))     [M2, HFd]
    gemm_mma<true, false, true><<<(M2 / TM) * (HFd / TN), 256, GEMM_SMEM>>>(
        yt_p, w_p + OFF_FW1, fb1, nullptr, big_p, M2, HFd, Ff, 16);

    // 8) out = h2 @ fw2^T + fb2                [B,N,OUT]
    gemm_mma<false, false, false><<<(M2 / TM) * (OUTF / TN), 256, GEMM_SMEM>>>(
        big_p, w_p + OFF_FW2, fb2, nullptr, out, M2, OUTF, HFd, 32);
}

// round 11
// speedup vs baseline: 3.9195x; 1.0911x over previous
#include <cuda_runtime.h>
#include <cub/cub.cuh>
#include <cstdint>

#define Bb   32
#define Nn   2048
#define Ff   1024
#define HSd  8192
#define HFd  4096
#define OUTF 1024
#define M1   (Bb * Ff)   // 32768 rows for sorted-MLP (K = Nn)
#define M2   (Bb * Nn)   // 65536 rows for feature-MLP (K = Ff)

// ---------------- static device scratch ----------------
__device__ float g_big[268435456]; // 1 GiB: h (M1 x HSd), reused as h2 (M2 x HFd)
__device__ float g_xt [67108864];  // xt [B,F,N], reused as y_s
__device__ float g_xs [67108864];  // xs [B,F,N] (tf32-rounded), reused as yg
__device__ float g_yt [67108864];  // yt [B,N,F] (tf32-rounded)
__device__ int   g_p  [67108864];  // permutation p [B,F,N]
__device__ float g_wts[41943040];  // tf32-rounded weights: sw1|sw2|fw1|fw2

#define OFF_SW1 0
#define OFF_SW2 16777216
#define OFF_FW1 33554432
#define OFF_FW2 37748736

// ================= PTX helpers (plain sm_103 — NO 'a' features) =================
__device__ __forceinline__ uint32_t smem_u32(const void* p) {
    uint32_t a;
    asm("{ .reg .u64 t; cvta.to.shared.u64 t, %1; cvt.u32.u64 %0, t; }" : "=r"(a) : "l"(p));
    return a;
}

#define CP_ASYNC16(s, g) \
    asm volatile("cp.async.cg.shared.global [%0], [%1], 16;\n" :: "r"(s), "l"(g) : "memory")
#define CP_COMMIT() asm volatile("cp.async.commit_group;\n" ::: "memory")
#define CP_WAIT1()  asm volatile("cp.async.wait_group 1;\n" ::: "memory")

// ldmatrix.x4: four 8x8 b16 tiles -> 4 regs; for tf32 this is a 16(row) x 8(tf32-col)
// fragment in exactly mma.m16n8k8 A-layout (or two stacked 8x8 B-fragments).
#define LDSM4(r0, r1, r2, r3, a) \
    asm volatile("ldmatrix.sync.aligned.m8n8.x4.shared.b16 {%0,%1,%2,%3}, [%4];" \
                 : "=r"(r0), "=r"(r1), "=r"(r2), "=r"(r3) : "r"(a))

__device__ __forceinline__ float f2tf_f(float f) {
    uint32_t r;
    asm("cvt.rna.tf32.f32 %0, %1;" : "=r"(r) : "f"(f));
    return __uint_as_float(r);
}

__device__ __forceinline__ void mma_tf32(float& d0, float& d1, float& d2, float& d3,
                                         uint32_t a0, uint32_t a1, uint32_t a2, uint32_t a3,
                                         uint32_t b0, uint32_t b1) {
    asm volatile("mma.sync.aligned.m16n8k8.row.col.f32.tf32.tf32.f32 "
                 "{%0,%1,%2,%3}, {%4,%5,%6,%7}, {%8,%9}, {%0,%1,%2,%3};"
                 : "+f"(d0), "+f"(d1), "+f"(d2), "+f"(d3)
                 : "r"(a0), "r"(a1), "r"(a2), "r"(a3), "r"(b0), "r"(b1));
}

// ---------------- weight pre-round: dst = tf32_round(src) ----------------
__global__ void round_copy(const float* __restrict__ src, float* __restrict__ dst, int n4) {
    int i = blockIdx.x * blockDim.x + threadIdx.x;
    if (i < n4) {
        float4 v = ((const float4*)src)[i];
        v.x = f2tf_f(v.x); v.y = f2tf_f(v.y); v.z = f2tf_f(v.z); v.w = f2tf_f(v.w);
        ((float4*)dst)[i] = v;
    }
}

// ================= tf32 mma.sync GEMM =================
// C[M,Nc] = epi(A @ W^T + bias (+skip)); A row-major [M,K] (pre-rounded to tf32),
// W row-major [Nc,K] (pre-rounded). CTA 128x128, BK=32, 3-stage cp.async,
// 256 thr = 2(m) x 4(n) warps, warp tile 64x32, 2 CTAs/SM, ldmatrix fragments.
#define TM 128
#define TN 128
#define BK 32
#define LDA 36                              // smem row stride (floats): bank-conflict-free
#define TILE_FLOATS (128 * LDA)             // 4608 floats = 18432 B per matrix
#define STAGE_FLOATS (2 * TILE_FLOATS)      // A then B
#define SM_BIAS_F 0                         // 128 floats
#define SM_STG0_F 256
#define GEMM_SMEM ((SM_STG0_F + 3 * STAGE_FLOATS) * 4)  // 111616 B

template<bool RELU, bool SKIP, bool ROUND>
__global__ void __launch_bounds__(256, 2) gemm_mma(
    const float* __restrict__ A, const float* __restrict__ W,
    const float* __restrict__ bias, const float* __restrict__ skip,
    float* __restrict__ C, int M, int Nc, int K, int superM)
{
    extern __shared__ float smem[];
    uint32_t sb = smem_u32(smem);
    int tid = threadIdx.x, wid = tid >> 5, lane = tid & 31;
    int wm = wid & 1, wn = wid >> 1;        // warp grid 2 x 4
    int gq = lane >> 2, lq = lane & 3;      // group-of-4 id, id-in-group

    // supertiled raster (m-fastest within superM column chunk)
    const int nTN = Nc / TN;
    int tilesPer = superM * nTN;
    int sid = blockIdx.x / tilesPer;
    int rem = blockIdx.x - sid * tilesPer;
    int mt  = sid * superM + (rem % superM);
    int nt  = rem / superM;
    int m0 = mt * TM, n0 = nt * TN;

    for (int i = tid; i < TN; i += 256) smem[SM_BIAS_F + i] = bias[n0 + i];

    // cp.async mapping: idx in [0,1024): row = idx>>3, 16B chunk = idx&7
    int r0 = tid >> 3, ch = tid & 7;
    const char* gA = (const char*)(A + (long)(m0 + r0) * K) + ch * 16;
    const char* gB = (const char*)(W + (long)(n0 + r0) * K) + ch * 16;
    long rowStep = (long)32 * K * 4;                // +32 rows (q step), bytes
    uint32_t sOffA = (uint32_t)(r0 * (LDA * 4) + ch * 16);
    int KS = K / BK;

#define LOAD_STAGE(s_, kblk_) do { \
        uint32_t sa_ = sb + (SM_STG0_F + (s_) * STAGE_FLOATS) * 4; \
        uint32_t sbm_ = sa_ + TILE_FLOATS * 4; \
        const char* pa_ = gA + (long)(kblk_) * 128; \
        const char* pb_ = gB + (long)(kblk_) * 128; \
        _Pragma("unroll") \
        for (int q = 0; q < 4; ++q) \
            CP_ASYNC16(sa_ + sOffA + q * (32 * LDA * 4), pa_ + q * rowStep); \
        _Pragma("unroll") \
        for (int q = 0; q < 4; ++q) \
            CP_ASYNC16(sbm_ + sOffA + q * (32 * LDA * 4), pb_ + q * rowStep); \
    } while (0)

    // prologue: stages 0..1
    LOAD_STAGE(0, 0); CP_COMMIT();
    LOAD_STAGE(1, 1); CP_COMMIT();

    float acc[4][4][4];
#pragma unroll
    for (int i = 0; i < 4; ++i)
#pragma unroll
        for (int j = 0; j < 4; ++j) {
            acc[i][j][0] = 0.f; acc[i][j][1] = 0.f;
            acc[i][j][2] = 0.f; acc[i][j][3] = 0.f;
        }

    // ---- ldmatrix per-thread base addresses (byte offsets within a stage) ----
    // A 16x8 fragment at (rowBase=wm*64+mf*16, kb=kk*8):
    //   matrix sel=lane>>3: rows +(sel&1)*8, cols +(sel>>1)*4; row-in-matrix = lane&7
    int t8 = lane & 7, sel = lane >> 3;
    uint32_t aBase = (uint32_t)(((wm * 64 + t8 + (sel & 1) * 8) * LDA + (sel >> 1) * 4) * 4);
    // B two stacked 8x8 fragments (nf pair p): matrices: 0=(nf0,kb) 1=(nf0,kb+4) 2=(nf1,kb) 3=(nf1,kb+4)
    uint32_t bBase = (uint32_t)(((wn * 32 + (sel >> 1) * 8 + t8) * LDA + (sel & 1) * 4) * 4);

    int stg = 0;
    for (int i = 0; i < KS; ++i) {
        CP_WAIT1();
        __syncthreads();
        int j = i + 2;
        if (j < KS) {
            int sn = stg + 2; if (sn >= 3) sn -= 3;
            LOAD_STAGE(sn, j);
        }
        CP_COMMIT();

        uint32_t sA = sb + (SM_STG0_F + stg * STAGE_FLOATS) * 4 + aBase;
        uint32_t sB = sb + (SM_STG0_F + stg * STAGE_FLOATS + TILE_FLOATS) * 4 + bBase;
#pragma unroll
        for (int kk = 0; kk < 4; ++kk) {
            uint32_t af[4][4];
#pragma unroll
            for (int mf = 0; mf < 4; ++mf)
                LDSM4(af[mf][0], af[mf][1], af[mf][2], af[mf][3],
                      sA + mf * (16 * LDA * 4) + kk * 32);
            uint32_t bf[4][2];
            LDSM4(bf[0][0], bf[0][1], bf[1][0], bf[1][1], sB + kk * 32);
            LDSM4(bf[2][0], bf[2][1], bf[3][0], bf[3][1], sB + 16 * LDA * 4 + kk * 32);
#pragma unroll
            for (int mf = 0; mf < 4; ++mf)
#pragma unroll
                for (int nf = 0; nf < 4; ++nf)
                    mma_tf32(acc[mf][nf][0], acc[mf][nf][1], acc[mf][nf][2], acc[mf][nf][3],
                             af[mf][0], af[mf][1], af[mf][2], af[mf][3],
                             bf[nf][0], bf[nf][1]);
        }
        ++stg; if (stg == 3) stg = 0;
    }

    // epilogue from registers
#pragma unroll
    for (int mf = 0; mf < 4; ++mf) {
        int ra = m0 + wm * 64 + mf * 16 + gq;
#pragma unroll
        for (int nf = 0; nf < 4; ++nf) {
            int cl = wn * 32 + nf * 8 + 2 * lq;      // local col
            long c0off = (long)ra * Nc + n0 + cl;
            long c1off = (long)(ra + 8) * Nc + n0 + cl;
            float b0 = smem[SM_BIAS_F + cl], b1 = smem[SM_BIAS_F + cl + 1];
            float2 o0, o1;
            o0.x = acc[mf][nf][0] + b0; o0.y = acc[mf][nf][1] + b1;
            o1.x = acc[mf][nf][2] + b0; o1.y = acc[mf][nf][3] + b1;
            if (SKIP) {
                float2 s0 = *(const float2*)(skip + c0off);
                float2 s1 = *(const float2*)(skip + c1off);
                o0.x += s0.x; o0.y += s0.y; o1.x += s1.x; o1.y += s1.y;
            }
            if (RELU) {
                o0.x = fmaxf(o0.x, 0.f); o0.y = fmaxf(o0.y, 0.f);
                o1.x = fmaxf(o1.x, 0.f); o1.y = fmaxf(o1.y, 0.f);
            }
            if (ROUND) {
                o0.x = f2tf_f(o0.x); o0.y = f2tf_f(o0.y);
                o1.x = f2tf_f(o1.x); o1.y = f2tf_f(o1.y);
            }
            *(float2*)(C + c0off) = o0;
            *(float2*)(C + c1off) = o1;
        }
    }
#undef LOAD_STAGE
}

// ---------------- transpose: in[B,R,C] -> out[B,C,R] ----------------
template<int R, int C, bool ROUND>
__global__ void transpose_t(const float* __restrict__ in, float* __restrict__ out) {
    __shared__ float tile[32][33];
    int b  = blockIdx.z;
    int r0 = blockIdx.y * 32;
    int c0 = blockIdx.x * 32;
    int tx = threadIdx.x, ty = threadIdx.y;  // (32, 8)
    const float* ib = in  + (long)b * R * C;
    float*       ob = out + (long)b * R * C;
#pragma unroll
    for (int i = 0; i < 32; i += 8)
        tile[ty + i][tx] = ib[(long)(r0 + ty + i) * C + c0 + tx];
    __syncthreads();
#pragma unroll
    for (int i = 0; i < 32; i += 8) {
        float v = tile[tx][ty + i];
        if (ROUND) v = f2tf_f(v);
        ob[(long)(c0 + ty + i) * R + r0 + tx] = v;
    }
}

// ---------------- per-row stable argsort (radix); writes tf32-rounded xs ----------------
__global__ void __launch_bounds__(512) sort_kernel(const float* __restrict__ xt,
                                                   float* __restrict__ xs,
                                                   int* __restrict__ p) {
    typedef cub::BlockRadixSort<unsigned int, 512, 4, int> BRS;
    __shared__ typename BRS::TempStorage ts;
    __shared__ float rowv[Nn];
    __shared__ int   inv[Nn];

    long row = blockIdx.x;
    const float* in = xt + row * Nn;

    float4 v4 = reinterpret_cast<const float4*>(in)[threadIdx.x];
    float vj[4] = {v4.x, v4.y, v4.z, v4.w};

    unsigned keys[4]; int vals[4];
#pragma unroll
    for (int j = 0; j < 4; ++j) {
        int idx = threadIdx.x * 4 + j;
        rowv[idx] = vj[j];
        unsigned u = __float_as_uint(vj[j]);
        u = (u & 0x80000000u) ? ~u : (u | 0x80000000u);  // order-preserving
        keys[j] = u; vals[j] = idx;
    }
    __syncthreads();
    BRS(ts).Sort(keys, vals);  // stable ascending, exact keys -> p matches reference
    __syncthreads();

    int4 pv;
    pv.x = vals[0]; pv.y = vals[1]; pv.z = vals[2]; pv.w = vals[3];
    reinterpret_cast<int4*>(p + row * Nn)[threadIdx.x] = pv;
#pragma unroll
    for (int j = 0; j < 4; ++j)
        inv[vals[j]] = threadIdx.x * 4 + j;
    __syncthreads();

    float4 o;
    o.x = f2tf_f(rowv[inv[threadIdx.x * 4 + 0]]);
    o.y = f2tf_f(rowv[inv[threadIdx.x * 4 + 1]]);
    o.z = f2tf_f(rowv[inv[threadIdx.x * 4 + 2]]);
    o.w = f2tf_f(rowv[inv[threadIdx.x * 4 + 3]]);
    reinterpret_cast<float4*>(xs + row * Nn)[threadIdx.x] = o;
}

// ---------------- per-row gather: yg[row, n] = y_s[row, p[row, n]] ----------------
__global__ void gather_kernel(const float* __restrict__ ys, const int* __restrict__ p,
                              float* __restrict__ yg) {
    __shared__ float sm[Nn];
    long row = blockIdx.x;
    for (int i = threadIdx.x; i < Nn; i += blockDim.x)
        sm[i] = ys[row * Nn + i];
    __syncthreads();
    for (int i = threadIdx.x; i < Nn; i += blockDim.x)
        yg[row * Nn + i] = sm[p[row * Nn + i]];
}

// ---------------- launch ----------------
extern "C" void kernel_launch(void* const* d_in, const int* in_sizes, int n_in,
                              void* d_out, int out_size) {
    const float* x   = (const float*)d_in[0];
    const float* sw1 = (const float*)d_in[1];
    const float* sb1 = (const float*)d_in[2];
    const float* sw2 = (const float*)d_in[3];
    const float* sb2 = (const float*)d_in[4];
    const float* fw1 = (const float*)d_in[5];
    const float* fb1 = (const float*)d_in[6];
    const float* fw2 = (const float*)d_in[7];
    const float* fb2 = (const float*)d_in[8];
    float* out = (float*)d_out;

    float *xt_p, *xs_p, *yt_p, *big_p, *w_p; int *p_p;
    cudaGetSymbolAddress((void**)&xt_p,  g_xt);
    cudaGetSymbolAddress((void**)&xs_p,  g_xs);
    cudaGetSymbolAddress((void**)&yt_p,  g_yt);
    cudaGetSymbolAddress((void**)&big_p, g_big);
    cudaGetSymbolAddress((void**)&w_p,   g_wts);
    cudaGetSymbolAddress((void**)&p_p,   g_p);

    cudaFuncSetAttribute(gemm_mma<true,  false, true >, cudaFuncAttributeMaxDynamicSharedMemorySize, GEMM_SMEM);
    cudaFuncSetAttribute(gemm_mma<false, true,  false>, cudaFuncAttributeMaxDynamicSharedMemorySize, GEMM_SMEM);
    cudaFuncSetAttribute(gemm_mma<false, false, false>, cudaFuncAttributeMaxDynamicSharedMemorySize, GEMM_SMEM);

    dim3 tb(32, 8);

    // 0) pre-round weights to tf32 (into static scratch)
    round_copy<<<(HSd * Nn / 4 + 255) / 256, 256>>>(sw1, w_p + OFF_SW1, HSd * Nn / 4);
    round_copy<<<(Nn * HSd / 4 + 255) / 256, 256>>>(sw2, w_p + OFF_SW2, Nn * HSd / 4);
    round_copy<<<(HFd * Ff / 4 + 255) / 256, 256>>>(fw1, w_p + OFF_FW1, HFd * Ff / 4);
    round_copy<<<(OUTF * HFd / 4 + 255) / 256, 256>>>(fw2, w_p + OFF_FW2, OUTF * HFd / 4);

    // 1) transpose x[B,N,F] -> xt[B,F,N] (exact — sort keys must match reference)
    transpose_t<Nn, Ff, false><<<dim3(Ff / 32, Nn / 32, Bb), tb>>>(x, xt_p);

    // 2) per-row sort: xs (tf32-rounded permuted values) + p (argsort)
    sort_kernel<<<M1, 512>>>(xt_p, xs_p, p_p);

    // 3) h = tf32(relu(xs @ sw1^T + sb1))      [M1, HSd]
    gemm_mma<true, false, true><<<(M1 / TM) * (HSd / TN), 256, GEMM_SMEM>>>(
        xs_p, w_p + OFF_SW1, sb1, nullptr, big_p, M1, HSd, Nn, 16);

    // 4) y_s = h @ sw2^T + sb2 + xs            [M1, Nn]  (into xt buffer)
    gemm_mma<false, true, false><<<(M1 / TM) * (Nn / TN), 256, GEMM_SMEM>>>(
        big_p, w_p + OFF_SW2, sb2, xs_p, xt_p, M1, Nn, HSd, 16);

    // 5) yg[row, n] = y_s[row, p[row, n]]      [B,F,N]   (into xs buffer)
    gather_kernel<<<M1, 256>>>(xt_p, p_p, xs_p);

    // 6) transpose yg[B,F,N] -> yt[B,N,F], tf32-rounded
    transpose_t<Ff, Nn, true><<<dim3(Nn / 32, Ff / 32, Bb), tb>>>(xs_p, yt_p);

    // 7) h2 = tf32(relu(yt @ fw1^T + fb1))     [M2, HFd]
    gemm_mma<true, false, true><<<(M2 / TM) * (HFd / TN), 256, GEMM_SMEM>>>(
        yt_p, w_p + OFF_FW1, fb1, nullptr, big_p, M2, HFd, Ff, 16);

    // 8) out = h2 @ fw2^T + fb2                [B,N,OUT]
    gemm_mma<false, false, false><<<(M2 / TM) * (OUTF / TN), 256, GEMM_SMEM>>>(
        big_p, w_p + OFF_FW2, fb2, nullptr, out, M2, OUTF, HFd, 32);
}